// round 9
// baseline (speedup 1.0000x reference)
#include <cuda_runtime.h>
#include <math.h>

#define B_SZ 512
#define T_SZ 512
#define IN_SZ 128
#define H_SZ 256
#define NB   128   // 8 batch-groups x 16 unit-slices; <=148 SMs => single wave

typedef unsigned long long ull;

// ---------------- scratch (static device globals; no allocation) ----------------
__device__ float g_h0[2][B_SZ * H_SZ];
__device__ float g_h1[2][B_SZ * H_SZ];
__device__ float g_o0[B_SZ * 256];
__device__ float g_o1[B_SZ * 256];
__device__ float g_z [B_SZ * 64];

// per-group barrier state (8 groups, 128B-padded; monotonic across replays)
__device__ unsigned g_gc[8 * 32];
__device__ volatile unsigned g_gp[8 * 32];

__device__ __forceinline__ float sigmoidf_(float x) { return 1.f / (1.f + expf(-x)); }

// packed f32x2 helpers (sm_103a FFMA2; PTX-only)
__device__ __forceinline__ ull pack2(float lo, float hi) {
    ull r; asm("mov.b64 %0, {%1, %2};" : "=l"(r) : "f"(lo), "f"(hi)); return r;
}
__device__ __forceinline__ float2 unpack2(ull p) {
    float2 v; asm("mov.b64 {%0, %1}, %2;" : "=f"(v.x), "=f"(v.y) : "l"(p)); return v;
}
#define FMA2(acc, a, b) asm("fma.rn.f32x2 %0, %1, %2, %0;" : "+l"(acc) : "l"(a), "l"(b))

// Monotonic group barrier over the 16 blocks sharing bg. __threadfence (gpu scope)
// emits CCTL.IVALL on sm_103a -> reader L1 invalidated, peer h-writes visible.
__device__ __forceinline__ void group_bar(int bg, unsigned& ph) {
    __syncthreads();
    if (threadIdx.x == 0) {
        __threadfence();
        unsigned p = ph;
        if (atomicAdd(&g_gc[bg * 32], 1u) == p * 16u + 15u) {
            __threadfence();
            g_gp[bg * 32] = p + 1u;
        } else {
            while (g_gp[bg * 32] < p + 1u) { }
            __threadfence();
        }
    }
    __syncthreads();
    ph += 1u;
}

// ---- load one weight slice (48 rows = 3 gates x 16 units) into padded SMEM ----
template<int K>
__device__ __forceinline__ void load_w(const float* __restrict__ W, int us,
                                       float* dst, int tid) {
    const int n4 = 48 * K / 4;
    for (int idx = tid; idx < n4; idx += 256) {
        int r = idx / (K / 4), c4 = idx % (K / 4);
        int grow = (r >> 4) * 256 + us * 16 + (r & 15);
        *(float4*)(dst + r * (K + 4) + c4 * 4) =
            *(const float4*)(W + (long)grow * K + c4 * 4);
    }
}

// ---- per-warp activation staging: warp w owns batch rows 8w..8w+7 ----
// lane -> (row = lane>>2, col4-block = lane&3); 4 float4 per lane = 8x64 tile.
__device__ __forceinline__ void ldw4(float4* v, const float* __restrict__ src,
                                     long rs, int kc, int row0, int lane) {
    const int r = row0 + (lane >> 2);
    const int cb = lane & 3;
    #pragma unroll
    for (int j = 0; j < 4; j++)
        v[j] = *(const float4*)(src + (long)r * rs + kc + (cb + j * 4) * 4);
}
__device__ __forceinline__ void stw4(float* dst, const float4* v, int lane) {
    const int r = lane >> 2;
    const int cb = lane & 3;
    #pragma unroll
    for (int j = 0; j < 4; j++)
        *(float4*)(dst + r * 64 + (cb + j * 4) * 4) = v[j];
}

// ---- one 64-K chunk: 3 gates x 4 batch, f32x2 K-packed accumulators ----
// xp: this thread's 4 batch rows (stride 64) in the warp-private buffer.
__device__ __forceinline__ void chunk_mm(const float* __restrict__ ws, int WP,
                                         const float* __restrict__ xp,
                                         int u_local, ull* a0, ull* a1, ull* a2) {
    const float* wp0 = ws + u_local * WP;
    const float* wp1 = wp0 + 16 * WP;
    const float* wp2 = wp1 + 16 * WP;
    #pragma unroll
    for (int k = 0; k < 64; k += 4) {
        const ulonglong2 w0 = *(const ulonglong2*)(wp0 + k);
        const ulonglong2 w1 = *(const ulonglong2*)(wp1 + k);
        const ulonglong2 w2 = *(const ulonglong2*)(wp2 + k);
        #pragma unroll
        for (int b = 0; b < 4; b++) {
            const ulonglong2 xv = *(const ulonglong2*)(xp + b * 64 + k);
            FMA2(a0[b], xv.x, w0.x); FMA2(a0[b], xv.y, w0.y);
            FMA2(a1[b], xv.x, w1.x); FMA2(a1[b], xv.y, w1.y);
            FMA2(a2[b], xv.x, w2.x); FMA2(a2[b], xv.y, w2.y);
        }
    }
}

// ---- one GRU layer for one timestep (weights in SMEM, per-warp x staging) ----
template<int K1, int WP1>
__device__ void gru_layer(
    const float* __restrict__ in1, long s1,            // ih input (64 x K1)
    const float* __restrict__ h_in,                    // (512,256)
    const float* wih, const float* whh,                // SMEM, padded
    float br, float bz, float bn, float bh,
    float* __restrict__ h_out, float* xw,              // xw = warp-private 1024 floats
    int lane, int warp, int half, int u_local, int u, int b0)
{
    ull ar[4], az[4], an_[4], ah[4];
    #pragma unroll
    for (int b = 0; b < 4; b++) {
        ar[b] = pack2(br, 0.f); az[b] = pack2(bz, 0.f);
        an_[b] = pack2(bn, 0.f); ah[b] = pack2(bh, 0.f);
    }

    const int row0 = b0 + warp * 8;
    constexpr int NC1 = K1 / 64;
    float4 v[4];
    ldw4(v, in1, s1, 0, row0, lane);
    int buf = 0;

    // ih phase (warp free-runs; only __syncwarp between STS and LDS)
    #pragma unroll 1
    for (int c = 0; c < NC1; c++) {
        stw4(xw + buf * 512, v, lane);
        __syncwarp();
        if (c + 1 < NC1) ldw4(v, in1, s1, (c + 1) * 64, row0, lane);
        else             ldw4(v, h_in, 256, 0, row0, lane);
        chunk_mm(wih + c * 64, WP1, xw + buf * 512 + half * 256, u_local, ar, az, an_);
        buf ^= 1;
    }
    // hh phase
    #pragma unroll 1
    for (int c = 0; c < 4; c++) {
        stw4(xw + buf * 512, v, lane);
        __syncwarp();
        if (c + 1 < 4) ldw4(v, h_in, 256, (c + 1) * 64, row0, lane);
        chunk_mm(whh + c * 64, 260, xw + buf * 512 + half * 256, u_local, ar, az, ah);
        buf ^= 1;
    }

    const int bgrp = warp * 2 + half;
    #pragma unroll
    for (int b = 0; b < 4; b++) {
        int bb = bgrp * 4 + b;
        float2 vr = unpack2(ar[b]);
        float2 vz = unpack2(az[b]);
        float2 vn = unpack2(an_[b]);
        float2 vh = unpack2(ah[b]);
        float r  = sigmoidf_(vr.x + vr.y);
        float z  = sigmoidf_(vz.x + vz.y);
        float n  = tanhf((vn.x + vn.y) + r * (vh.x + vh.y));
        float hp = h_in[(long)(b0 + bb) * 256 + u];
        h_out[(long)(b0 + bb) * 256 + u] = (1.f - z) * n + z * hp;
    }
}

// ---------------- persistent GRU scan: weights SMEM-resident ----------------
__global__ void __launch_bounds__(256) gru_persistent(
    const float* __restrict__ x,
    const float* __restrict__ W0i, const float* __restrict__ W0h,
    const float* __restrict__ b0i, const float* __restrict__ b0h,
    const float* __restrict__ W1i, const float* __restrict__ W1h,
    const float* __restrict__ b1i, const float* __restrict__ b1h)
{
    extern __shared__ float sm[];
    float* w0i = sm;
    float* w0h = sm + 6336;
    float* w1i = sm + 18816;
    float* w1h = sm + 31296;
    float* xbuf = sm + 43776;      // 8 warps x 1024 floats (double-buffered 8x64)

    const int tid     = threadIdx.x;
    const int bg      = blockIdx.x >> 4;   // 8 groups of 64 batch
    const int us      = blockIdx.x & 15;   // 16 unit-slices of 16 units
    const int lane    = tid & 31;
    const int warp    = tid >> 5;
    const int half    = (tid >> 4) & 1;
    const int u_local = tid & 15;
    const int u       = us * 16 + u_local;
    const int b0      = bg * 64;
    float* xw = xbuf + warp * 1024;

    load_w<128>(W0i, us, w0i, tid);
    load_w<256>(W0h, us, w0h, tid);
    load_w<256>(W1i, us, w1i, tid);
    load_w<256>(W1h, us, w1h, tid);

    // zero initial hidden states (buffer 0): this block's share of its bg rows
    {
        int off = bg * 16384 + us * 1024 + tid * 4;
        float4 z = make_float4(0.f, 0.f, 0.f, 0.f);
        *(float4*)&g_h0[0][off] = z;
        *(float4*)&g_h1[0][off] = z;
    }
    unsigned ph = g_gp[bg * 32];
    group_bar(bg, ph);  // zeros visible in group; weights are block-local

    const float br0 = b0i[u]       + b0h[u];
    const float bz0 = b0i[256 + u] + b0h[256 + u];
    const float bn0 = b0i[512 + u];
    const float bh0 = b0h[512 + u];
    const float br1 = b1i[u]       + b1h[u];
    const float bz1 = b1i[256 + u] + b1h[256 + u];
    const float bn1 = b1i[512 + u];
    const float bh1 = b1h[512 + u];

    const long HB = (long)B_SZ * H_SZ;
    for (int t = 0; t < T_SZ; t++) {
        const int r = t & 1, w = r ^ 1;
        gru_layer<128, 132>(x + (long)t * IN_SZ, (long)T_SZ * IN_SZ,
                            &g_h0[0][0] + r * HB,
                            w0i, w0h, br0, bz0, bn0, bh0,
                            &g_h0[0][0] + w * HB, xw,
                            lane, warp, half, u_local, u, b0);
        group_bar(bg, ph);   // peers' h0(t) ready; buffer rotation covers the rest
        gru_layer<256, 260>(&g_h0[0][0] + w * HB, 256L,
                            &g_h1[0][0] + r * HB,
                            w1i, w1h, br1, bz1, bn1, bh1,
                            &g_h1[0][0] + w * HB, xw,
                            lane, warp, half, u_local, u, b0);
    }
    // final h1 (t=511 odd -> w=0) lives in g_h1[0]
}

// ---------- LSTM heads: warp-per-2-outputs, lanes split K (coalesced) ----------
__global__ void __launch_bounds__(256) lstm_head_kernel(
    const float* __restrict__ s,
    const float* __restrict__ Wf, const float* __restrict__ bif, const float* __restrict__ bhf,
    const float* __restrict__ Wr, const float* __restrict__ bir, const float* __restrict__ bhr,
    float* __restrict__ out)
{
    __shared__ float ss[256];
    const int b = blockIdx.x, tid = threadIdx.x;
    const int warp = tid >> 5, lane = tid & 31;
    ss[tid] = s[b * 256 + tid];
    __syncthreads();

    #pragma unroll 1
    for (int oo = 0; oo < 32; oo += 2) {
        int idx = warp * 32 + oo;          // pair shares the same head
        int hd = idx >> 7, j0 = idx & 127, j1 = j0 + 1;
        const float* W  = hd ? Wr  : Wf;
        const float* bi = hd ? bir : bif;
        const float* bh = hd ? bhr : bhf;
        float di0 = 0.f, dg0 = 0.f, do0 = 0.f;
        float di1 = 0.f, dg1 = 0.f, do1 = 0.f;
        #pragma unroll
        for (int kk = 0; kk < 8; kk++) {
            int k = kk * 32 + lane;
            float sv = ss[k];
            di0 += sv * W[(long)j0 * 256 + k];
            di1 += sv * W[(long)j1 * 256 + k];
            dg0 += sv * W[(long)(256 + j0) * 256 + k];
            dg1 += sv * W[(long)(256 + j1) * 256 + k];
            do0 += sv * W[(long)(384 + j0) * 256 + k];
            do1 += sv * W[(long)(384 + j1) * 256 + k];
        }
        #pragma unroll
        for (int off = 16; off; off >>= 1) {
            di0 += __shfl_xor_sync(0xffffffffu, di0, off);
            di1 += __shfl_xor_sync(0xffffffffu, di1, off);
            dg0 += __shfl_xor_sync(0xffffffffu, dg0, off);
            dg1 += __shfl_xor_sync(0xffffffffu, dg1, off);
            do0 += __shfl_xor_sync(0xffffffffu, do0, off);
            do1 += __shfl_xor_sync(0xffffffffu, do1, off);
        }
        if (lane == 0) {
            di0 += bi[j0]       + bh[j0];
            dg0 += bi[256 + j0] + bh[256 + j0];
            do0 += bi[384 + j0] + bh[384 + j0];
            float c0 = sigmoidf_(di0) * tanhf(dg0);
            out[b * 256 + hd * 128 + j0] = sigmoidf_(do0) * tanhf(c0);
            di1 += bi[j1]       + bh[j1];
            dg1 += bi[256 + j1] + bh[256 + j1];
            do1 += bi[384 + j1] + bh[384 + j1];
            float c1 = sigmoidf_(di1) * tanhf(dg1);
            out[b * 256 + hd * 128 + j1] = sigmoidf_(do1) * tanhf(c1);
        }
    }
}

// ---------------- KAN: cubic B-spline basis (8 bases) ----------
__device__ __forceinline__ void bspl8(float x, float* bv) {
    const float h = 0.4f;
    float p[12];
    #pragma unroll
    for (int m = 0; m < 12; m++) p[m] = (float)(m - 3) * h - 1.0f;
    float b[11];
    #pragma unroll
    for (int j = 0; j < 11; j++) b[j] = (x >= p[j] && x < p[j + 1]) ? 1.f : 0.f;
    #pragma unroll
    for (int k = 1; k <= 3; k++) {
        #pragma unroll
        for (int j = 0; j < 11 - k; j++) {
            b[j] = (x - p[j]) / (p[j + k] - p[j]) * b[j]
                 + (p[j + k + 1] - x) / (p[j + k + 1] - p[j + 1]) * b[j + 1];
        }
    }
    #pragma unroll
    for (int j = 0; j < 8; j++) bv[j] = b[j];
}

// kan1: warp per 2 outputs in flight, lanes split the 256 inputs
__global__ void __launch_bounds__(256) kan1_kernel(
    const float* __restrict__ in,
    const float* __restrict__ base_w,
    const float* __restrict__ spline_w,
    const float* __restrict__ scaler,
    float* __restrict__ out)
{
    __shared__ float silu_s[256];
    __shared__ float bsp_s[256][9];   // pad 9: kills bank conflicts
    const int b = blockIdx.x, tid = threadIdx.x;
    const int warp = tid >> 5, lane = tid & 31;
    {
        float xv = in[b * 256 + tid];
        silu_s[tid] = xv / (1.f + expf(-xv));
        float bv[8]; bspl8(xv, bv);
        #pragma unroll
        for (int k = 0; k < 8; k++) bsp_s[tid][k] = bv[k];
    }
    __syncthreads();
    #pragma unroll 1
    for (int o = warp * 8; o < warp * 8 + 8; o += 2) {
        float accA = 0.f, accB = 0.f;
        #pragma unroll
        for (int ii = 0; ii < 8; ii++) {
            int i = ii * 32 + lane;
            float si = silu_s[i];
            accA += si * base_w[o * 256 + i];
            accB += si * base_w[(o + 1) * 256 + i];
            const float4* spA = (const float4*)(spline_w + ((long)o * 256 + i) * 8);
            const float4* spB = (const float4*)(spline_w + ((long)(o + 1) * 256 + i) * 8);
            float4 a0 = spA[0], a1 = spA[1], b0 = spB[0], b1 = spB[1];
            float bs0 = bsp_s[i][0], bs1 = bsp_s[i][1], bs2 = bsp_s[i][2], bs3 = bsp_s[i][3];
            float bs4 = bsp_s[i][4], bs5 = bsp_s[i][5], bs6 = bsp_s[i][6], bs7 = bsp_s[i][7];
            float sA = bs0 * a0.x + bs1 * a0.y + bs2 * a0.z + bs3 * a0.w
                     + bs4 * a1.x + bs5 * a1.y + bs6 * a1.z + bs7 * a1.w;
            float sB = bs0 * b0.x + bs1 * b0.y + bs2 * b0.z + bs3 * b0.w
                     + bs4 * b1.x + bs5 * b1.y + bs6 * b1.z + bs7 * b1.w;
            accA += scaler[o * 256 + i] * sA;
            accB += scaler[(o + 1) * 256 + i] * sB;
        }
        #pragma unroll
        for (int off = 16; off; off >>= 1) {
            accA += __shfl_xor_sync(0xffffffffu, accA, off);
            accB += __shfl_xor_sync(0xffffffffu, accB, off);
        }
        if (lane == 0) { out[b * 64 + o] = accA; out[b * 64 + o + 1] = accB; }
    }
}

// kan2: NIN=64, NOUT=10 (tiny)
__global__ void __launch_bounds__(64) kan2_kernel(
    const float* __restrict__ in,
    const float* __restrict__ base_w,
    const float* __restrict__ spline_w,
    const float* __restrict__ scaler,
    float* __restrict__ out)
{
    __shared__ float silu_s[64];
    __shared__ float bsp_s[64][9];
    const int b = blockIdx.x, tid = threadIdx.x;
    {
        float xv = in[b * 64 + tid];
        silu_s[tid] = xv / (1.f + expf(-xv));
        float bv[8]; bspl8(xv, bv);
        #pragma unroll
        for (int k = 0; k < 8; k++) bsp_s[tid][k] = bv[k];
    }
    __syncthreads();
    const int warp = tid >> 5, lane = tid & 31;
    if (warp < 2) {
        #pragma unroll 1
        for (int o = warp * 5; o < warp * 5 + 5; o++) {
            float acc = 0.f;
            #pragma unroll
            for (int ii = 0; ii < 2; ii++) {
                int i = ii * 32 + lane;
                acc += silu_s[i] * base_w[o * 64 + i];
                const float4* sp = (const float4*)(spline_w + ((long)o * 64 + i) * 8);
                float4 s0 = sp[0], s1 = sp[1];
                float s8 = bsp_s[i][0] * s0.x + bsp_s[i][1] * s0.y
                         + bsp_s[i][2] * s0.z + bsp_s[i][3] * s0.w
                         + bsp_s[i][4] * s1.x + bsp_s[i][5] * s1.y
                         + bsp_s[i][6] * s1.z + bsp_s[i][7] * s1.w;
                acc += scaler[o * 64 + i] * s8;
            }
            #pragma unroll
            for (int off = 16; off; off >>= 1) acc += __shfl_xor_sync(0xffffffffu, acc, off);
            if (lane == 0) out[b * 10 + o] = acc;
        }
    }
}

// ---------------- launch ----------------
extern "C" void kernel_launch(void* const* d_in, const int* in_sizes, int n_in,
                              void* d_out, int out_size) {
    const float* x        = (const float*)d_in[0];
    const float* g0_wih   = (const float*)d_in[1];
    const float* g0_whh   = (const float*)d_in[2];
    const float* g0_bih   = (const float*)d_in[3];
    const float* g0_bhh   = (const float*)d_in[4];
    const float* g1_wih   = (const float*)d_in[5];
    const float* g1_whh   = (const float*)d_in[6];
    const float* g1_bih   = (const float*)d_in[7];
    const float* g1_bhh   = (const float*)d_in[8];
    const float* lw_ih0   = (const float*)d_in[9];
    const float* lb_ih0   = (const float*)d_in[11];
    const float* lb_hh0   = (const float*)d_in[12];
    const float* lw_ih0r  = (const float*)d_in[13];
    const float* lb_ih0r  = (const float*)d_in[15];
    const float* lb_hh0r  = (const float*)d_in[16];
    const float* lw_ih1   = (const float*)d_in[17];
    const float* lb_ih1   = (const float*)d_in[19];
    const float* lb_hh1   = (const float*)d_in[20];
    const float* lw_ih1r  = (const float*)d_in[21];
    const float* lb_ih1r  = (const float*)d_in[23];
    const float* lb_hh1r  = (const float*)d_in[24];
    const float* kan1_base   = (const float*)d_in[25];
    const float* kan1_spline = (const float*)d_in[26];
    const float* kan1_scaler = (const float*)d_in[27];
    const float* kan2_base   = (const float*)d_in[28];
    const float* kan2_spline = (const float*)d_in[29];
    const float* kan2_scaler = (const float*)d_in[30];

    float *h1, *o0, *o1, *zz;
    cudaGetSymbolAddress((void**)&h1, g_h1);
    cudaGetSymbolAddress((void**)&o0, g_o0);
    cudaGetSymbolAddress((void**)&o1, g_o1);
    cudaGetSymbolAddress((void**)&zz, g_z);

    const int smem = (6336 + 12480 + 12480 + 12480 + 8192) * 4;  // 207,872 B
    cudaFuncSetAttribute(gru_persistent, cudaFuncAttributeMaxDynamicSharedMemorySize, smem);

    gru_persistent<<<NB, 256, smem>>>(x,
                                      g0_wih, g0_whh, g0_bih, g0_bhh,
                                      g1_wih, g1_whh, g1_bih, g1_bhh);

    lstm_head_kernel<<<512, 256>>>(h1, lw_ih0, lb_ih0, lb_hh0,
                                   lw_ih0r, lb_ih0r, lb_hh0r, o0);
    lstm_head_kernel<<<512, 256>>>(o0, lw_ih1, lb_ih1, lb_hh1,
                                   lw_ih1r, lb_ih1r, lb_hh1r, o1);
    kan1_kernel<<<512, 256>>>(o1, kan1_base, kan1_spline, kan1_scaler, zz);
    kan2_kernel<<<512, 64>>>(zz, kan2_base, kan2_spline, kan2_scaler, (float*)d_out);
}

// round 11
// speedup vs baseline: 1.5052x; 1.5052x over previous
#include <cuda_runtime.h>
#include <cuda_bf16.h>
#include <mma.h>
#include <math.h>
using namespace nvcuda;

#define B_SZ 512
#define T_SZ 512
#define IN_SZ 128
#define NB 128
#define NT 384
typedef unsigned int u32;
typedef __nv_bfloat16 bf16;

// ---------------- scratch (static device globals; no allocation) ----------------
__device__ __align__(16) bf16 g_xh[B_SZ * T_SZ * IN_SZ];
__device__ __align__(16) bf16 g_xl[B_SZ * T_SZ * IN_SZ];
__device__ __align__(16) bf16 g_h0h[2][B_SZ * 256], g_h0l[2][B_SZ * 256];
__device__ __align__(16) bf16 g_h1h[2][B_SZ * 256], g_h1l[2][B_SZ * 256];
__device__ float g_o0[B_SZ * 256], g_o1[B_SZ * 256], g_z[B_SZ * 64];
__device__ unsigned g_gc[8 * 32];
__device__ volatile unsigned g_gp[8 * 32];

__device__ __forceinline__ float sigmoidf_(float x) { return 1.f / (1.f + expf(-x)); }

// ---------------- smem byte offsets ----------------
#define SM_BIAS 0        // 128 floats
#define SM_X    512      // X hi: 64 x 72 bf16 = 9216 B
#define SM_XLO  9728     // X lo: 9216 B
#define SM_D0   18944    // 64 x 52 f32 = 13312 B (ih gates)
#define SM_D1   32256    // 13312 B (hh gates)
#define SM_W    45568    // 8 weight regions, 178176 B
#define WO_L0I_H 0
#define WO_L0I_L 13056
#define WO_L0H_H 26112
#define WO_L0H_L 51456
#define WO_L1I_H 76800
#define WO_L1I_L 102144
#define WO_L1H_H 127488
#define WO_L1H_L 152832
#define SMEM_TOTAL 223744

// Monotonic group barrier over the 16 blocks sharing bg (reader-side
// __threadfence -> CCTL.IVALL invalidates this SM's L1; same scheme as R6).
__device__ __forceinline__ void group_bar(int bg, unsigned& ph) {
    __syncthreads();
    if (threadIdx.x == 0) {
        __threadfence();
        unsigned p = ph;
        if (atomicAdd(&g_gc[bg * 32], 1u) == p * 16u + 15u) {
            __threadfence();
            g_gp[bg * 32] = p + 1u;
        } else {
            while (g_gp[bg * 32] < p + 1u) { }
            __threadfence();
        }
    }
    __syncthreads();
    ph += 1u;
}

// weight slice (48 rows = 3 gates x 16 units) split into bf16 hi/lo, ld = K+8
__device__ void wsplit(const float* __restrict__ W, int K, int us,
                       char* dh, char* dl, int tid) {
    const int wld = K + 8;
    for (int i = tid; i < 48 * K; i += NT) {
        int n = i / K, k = i % K;
        float w = W[(long)((n >> 4) * 256 + us * 16 + (n & 15)) * K + k];
        bf16 h = __float2bfloat16(w);
        bf16 l = __float2bfloat16(w - __bfloat162float(h));
        ((bf16*)dh)[n * wld + k] = h;
        ((bf16*)dl)[n * wld + k] = l;
    }
}

// ---- one GEMM phase: nch 64-K chunks, acc = sum of 3 bf16 products ----
__device__ void phase_wmma(const bf16* __restrict__ srch, const bf16* __restrict__ srcl,
                           long rs, int nch, char* sm,
                           u32 wh_off, u32 wl_off, int wld, float* D,
                           int b0, int tid, int mt, int nt) {
    bf16* Xhi = (bf16*)(sm + SM_X);
    bf16* Xlo = (bf16*)(sm + SM_XLO);
    const bf16* Whi = (const bf16*)(sm + SM_W + wh_off);
    const bf16* Wlo = (const bf16*)(sm + SM_W + wl_off);

    wmma::fragment<wmma::accumulator, 16, 16, 16, float> acc;
    wmma::fill_fragment(acc, 0.0f);

    for (int c = 0; c < nch; c++) {
        // hoist global loads (hi for idx<512, lo for 512..1023)
        uint4 v[3];
        #pragma unroll
        for (int i = 0; i < 3; i++) {
            int idx = tid + i * NT;
            if (idx < 1024) {
                const bf16* s = (idx & 512) ? srcl : srch;
                int vv = idx & 511, row = vv >> 3, c8 = vv & 7;
                v[i] = *(const uint4*)(s + (long)(b0 + row) * rs + c * 64 + c8 * 8);
            }
        }
        __syncthreads();   // prior chunk's fragment loads complete
        #pragma unroll
        for (int i = 0; i < 3; i++) {
            int idx = tid + i * NT;
            if (idx < 1024) {
                bf16* d = (idx & 512) ? Xlo : Xhi;
                int vv = idx & 511, row = vv >> 3, c8 = vv & 7;
                *(uint4*)(d + row * 72 + c8 * 8) = v[i];
            }
        }
        __syncthreads();   // staged tile visible
        #pragma unroll
        for (int kt = 0; kt < 4; kt++) {
            wmma::fragment<wmma::matrix_a, 16, 16, 16, bf16, wmma::row_major> Ah, Al;
            wmma::fragment<wmma::matrix_b, 16, 16, 16, bf16, wmma::col_major> Bh, Bl;
            wmma::load_matrix_sync(Ah, Xhi + mt * 16 * 72 + kt * 16, 72);
            wmma::load_matrix_sync(Al, Xlo + mt * 16 * 72 + kt * 16, 72);
            wmma::load_matrix_sync(Bh, Whi + (long)nt * 16 * wld + c * 64 + kt * 16, wld);
            wmma::load_matrix_sync(Bl, Wlo + (long)nt * 16 * wld + c * 64 + kt * 16, wld);
            wmma::mma_sync(acc, Ah, Bh, acc);
            wmma::mma_sync(acc, Ah, Bl, acc);
            wmma::mma_sync(acc, Al, Bh, acc);
        }
    }
    wmma::store_matrix_sync(D + mt * 16 * 52 + nt * 16, acc, 52, wmma::mem_row_major);
}

// ---- epilogue: gate math on D0 (ih) + D1 (hh), h written as bf16 hi/lo ----
__device__ void epi(char* sm, int L,
                    const bf16* __restrict__ hih, const bf16* __restrict__ hil,
                    bf16* __restrict__ hoh, bf16* __restrict__ hol,
                    int b0, int us, int tid) {
    __syncthreads();   // D stores visible
    const float* D0 = (const float*)(sm + SM_D0);
    const float* D1 = (const float*)(sm + SM_D1);
    const float* sb = (const float*)(sm + SM_BIAS) + L * 64;
    if (tid < 256) {
        const int ul = tid & 15, bb0 = tid >> 4;
        #pragma unroll
        for (int q = 0; q < 4; q++) {
            int bb = bb0 + q * 16;
            float r = sigmoidf_(D0[bb * 52 + ul] + D1[bb * 52 + ul] + sb[ul]);
            float z = sigmoidf_(D0[bb * 52 + 16 + ul] + D1[bb * 52 + 16 + ul] + sb[16 + ul]);
            float n = tanhf(D0[bb * 52 + 32 + ul] + sb[32 + ul]
                            + r * (D1[bb * 52 + 32 + ul] + sb[48 + ul]));
            long gi = (long)(b0 + bb) * 256 + us * 16 + ul;
            float hp = __bfloat162float(hih[gi]) + __bfloat162float(hil[gi]);
            float h = (1.f - z) * n + z * hp;
            bf16 hb = __float2bfloat16(h);
            hoh[gi] = hb;
            hol[gi] = __float2bfloat16(h - __bfloat162float(hb));
        }
    }
}

// one-shot: split x into bf16 hi/lo global arrays
__global__ void __launch_bounds__(256) xsplit_kernel(const float* __restrict__ x) {
    long i0 = ((long)blockIdx.x * 256 + threadIdx.x) * 16;
    #pragma unroll
    for (int j = 0; j < 4; j++) {
        float4 v = *(const float4*)(x + i0 + j * 4);
        bf16 h[4], l[4];
        h[0] = __float2bfloat16(v.x); l[0] = __float2bfloat16(v.x - __bfloat162float(h[0]));
        h[1] = __float2bfloat16(v.y); l[1] = __float2bfloat16(v.y - __bfloat162float(h[1]));
        h[2] = __float2bfloat16(v.z); l[2] = __float2bfloat16(v.z - __bfloat162float(h[2]));
        h[3] = __float2bfloat16(v.w); l[3] = __float2bfloat16(v.w - __bfloat162float(h[3]));
        *(uint2*)(g_xh + i0 + j * 4) = *(uint2*)h;
        *(uint2*)(g_xl + i0 + j * 4) = *(uint2*)l;
    }
}

// ---------------- persistent GRU scan, wmma engine ----------------
__global__ void __launch_bounds__(NT) gru_tc(
    const float* __restrict__ W0i, const float* __restrict__ W0h,
    const float* __restrict__ b0i, const float* __restrict__ b0h,
    const float* __restrict__ W1i, const float* __restrict__ W1h,
    const float* __restrict__ b1i, const float* __restrict__ b1h) {
    extern __shared__ char sm[];
    const int tid = threadIdx.x;
    const int bg = blockIdx.x >> 4, us = blockIdx.x & 15;
    const int b0 = bg * 64;
    const int warp = tid >> 5, mt = warp & 3, nt = warp >> 2;
    float* sbias = (float*)(sm + SM_BIAS);
    float* D0 = (float*)(sm + SM_D0);
    float* D1 = (float*)(sm + SM_D1);

    wsplit(W0i, 128, us, sm + SM_W + WO_L0I_H, sm + SM_W + WO_L0I_L, tid);
    wsplit(W0h, 256, us, sm + SM_W + WO_L0H_H, sm + SM_W + WO_L0H_L, tid);
    wsplit(W1i, 256, us, sm + SM_W + WO_L1I_H, sm + SM_W + WO_L1I_L, tid);
    wsplit(W1h, 256, us, sm + SM_W + WO_L1H_H, sm + SM_W + WO_L1H_L, tid);
    if (tid < 16) {
        int u = us * 16 + tid;
        sbias[tid]      = b0i[u] + b0h[u];
        sbias[16 + tid] = b0i[256 + u] + b0h[256 + u];
        sbias[32 + tid] = b0i[512 + u];
        sbias[48 + tid] = b0h[512 + u];
        sbias[64 + tid] = b1i[u] + b1h[u];
        sbias[80 + tid] = b1i[256 + u] + b1h[256 + u];
        sbias[96 + tid] = b1i[512 + u];
        sbias[112 + tid] = b1h[512 + u];
    }
    // zero initial hidden states (buffer 0): this CTA's 64 rows x 16 units
    for (int i = tid; i < 128; i += NT) {
        int row = i >> 1, hf = i & 1;
        long off = (long)(b0 + row) * 256 + us * 16 + hf * 8;
        uint4 z = make_uint4(0, 0, 0, 0);
        *(uint4*)(g_h0h[0] + off) = z;
        *(uint4*)(g_h0l[0] + off) = z;
        *(uint4*)(g_h1h[0] + off) = z;
        *(uint4*)(g_h1l[0] + off) = z;
    }
    __syncthreads();
    unsigned ph = g_gp[bg * 32];
    group_bar(bg, ph);

    for (int t = 0; t < T_SZ; t++) {
        const int r = t & 1, w = r ^ 1;
        // layer 0
        phase_wmma(g_xh + (long)t * IN_SZ, g_xl + (long)t * IN_SZ, (long)T_SZ * IN_SZ,
                   2, sm, WO_L0I_H, WO_L0I_L, 136, D0, b0, tid, mt, nt);
        phase_wmma(g_h0h[r], g_h0l[r], 256,
                   4, sm, WO_L0H_H, WO_L0H_L, 264, D1, b0, tid, mt, nt);
        epi(sm, 0, g_h0h[r], g_h0l[r], g_h0h[w], g_h0l[w], b0, us, tid);
        group_bar(bg, ph);   // peers' h0(t) visible; double-buffered h covers the rest
        // layer 1
        phase_wmma(g_h0h[w], g_h0l[w], 256,
                   4, sm, WO_L1I_H, WO_L1I_L, 264, D0, b0, tid, mt, nt);
        phase_wmma(g_h1h[r], g_h1l[r], 256,
                   4, sm, WO_L1H_H, WO_L1H_L, 264, D1, b0, tid, mt, nt);
        epi(sm, 1, g_h1h[r], g_h1l[r], g_h1h[w], g_h1l[w], b0, us, tid);
    }
    // final h1 (t=511 odd -> w=0) lives in buffer 0
}

// ---------------- tails ----------------
__global__ void __launch_bounds__(256) lstm_head_kernel(
    const bf16* __restrict__ sh, const bf16* __restrict__ sl, const float* __restrict__ sf,
    const float* __restrict__ Wf, const float* __restrict__ bif, const float* __restrict__ bhf,
    const float* __restrict__ Wr, const float* __restrict__ bir, const float* __restrict__ bhr,
    float* __restrict__ out) {
    __shared__ float ss[256];
    const int b = blockIdx.x, tid = threadIdx.x;
    const int warp = tid >> 5, lane = tid & 31;
    ss[tid] = sh ? (__bfloat162float(sh[b * 256 + tid]) + __bfloat162float(sl[b * 256 + tid]))
                 : sf[b * 256 + tid];
    __syncthreads();
    #pragma unroll 1
    for (int oo = 0; oo < 32; oo++) {
        int idx = warp * 32 + oo;
        int hd = idx >> 7, j = idx & 127;
        const float* W = hd ? Wr : Wf;
        const float* bi = hd ? bir : bif;
        const float* bh = hd ? bhr : bhf;
        float di = 0.f, dg = 0.f, doo = 0.f;
        #pragma unroll
        for (int kk = 0; kk < 8; kk++) {
            int k = kk * 32 + lane;
            float sv = ss[k];
            di  += sv * W[(long)j * 256 + k];
            dg  += sv * W[(long)(256 + j) * 256 + k];
            doo += sv * W[(long)(384 + j) * 256 + k];
        }
        #pragma unroll
        for (int off = 16; off; off >>= 1) {
            di  += __shfl_xor_sync(0xffffffffu, di,  off);
            dg  += __shfl_xor_sync(0xffffffffu, dg,  off);
            doo += __shfl_xor_sync(0xffffffffu, doo, off);
        }
        if (lane == 0) {
            di  += bi[j] + bh[j];
            dg  += bi[256 + j] + bh[256 + j];
            doo += bi[384 + j] + bh[384 + j];
            float c = sigmoidf_(di) * tanhf(dg);
            out[b * 256 + hd * 128 + j] = sigmoidf_(doo) * tanhf(c);
        }
    }
}

__device__ __forceinline__ void bspl8(float x, float* bv) {
    const float h = 0.4f;
    float p[12];
    #pragma unroll
    for (int m = 0; m < 12; m++) p[m] = (float)(m - 3) * h - 1.0f;
    float b[11];
    #pragma unroll
    for (int j = 0; j < 11; j++) b[j] = (x >= p[j] && x < p[j + 1]) ? 1.f : 0.f;
    #pragma unroll
    for (int k = 1; k <= 3; k++)
        #pragma unroll
        for (int j = 0; j < 11 - k; j++)
            b[j] = (x - p[j]) / (p[j + k] - p[j]) * b[j]
                 + (p[j + k + 1] - x) / (p[j + k + 1] - p[j + 1]) * b[j + 1];
    #pragma unroll
    for (int j = 0; j < 8; j++) bv[j] = b[j];
}

__global__ void __launch_bounds__(256) kan1_kernel(
    const float* __restrict__ in, const float* __restrict__ base_w,
    const float* __restrict__ spline_w, const float* __restrict__ scaler,
    float* __restrict__ out) {
    __shared__ float silu_s[256];
    __shared__ float bsp_s[256][9];
    const int b = blockIdx.x, tid = threadIdx.x;
    const int warp = tid >> 5, lane = tid & 31;
    {
        float xv = in[b * 256 + tid];
        silu_s[tid] = xv / (1.f + expf(-xv));
        float bv[8]; bspl8(xv, bv);
        #pragma unroll
        for (int k = 0; k < 8; k++) bsp_s[tid][k] = bv[k];
    }
    __syncthreads();
    #pragma unroll 1
    for (int o = warp * 8; o < warp * 8 + 8; o++) {
        float acc = 0.f;
        #pragma unroll
        for (int ii = 0; ii < 8; ii++) {
            int i = ii * 32 + lane;
            acc += silu_s[i] * base_w[o * 256 + i];
            const float4* sp = (const float4*)(spline_w + ((long)o * 256 + i) * 8);
            float4 s0 = sp[0], s1 = sp[1];
            float s8 = bsp_s[i][0] * s0.x + bsp_s[i][1] * s0.y + bsp_s[i][2] * s0.z + bsp_s[i][3] * s0.w
                     + bsp_s[i][4] * s1.x + bsp_s[i][5] * s1.y + bsp_s[i][6] * s1.z + bsp_s[i][7] * s1.w;
            acc += scaler[o * 256 + i] * s8;
        }
        #pragma unroll
        for (int off = 16; off; off >>= 1) acc += __shfl_xor_sync(0xffffffffu, acc, off);
        if (lane == 0) out[b * 64 + o] = acc;
    }
}

__global__ void __launch_bounds__(64) kan2_kernel(
    const float* __restrict__ in, const float* __restrict__ base_w,
    const float* __restrict__ spline_w, const float* __restrict__ scaler,
    float* __restrict__ out) {
    __shared__ float silu_s[64];
    __shared__ float bsp_s[64][9];
    const int b = blockIdx.x, tid = threadIdx.x;
    {
        float xv = in[b * 64 + tid];
        silu_s[tid] = xv / (1.f + expf(-xv));
        float bv[8]; bspl8(xv, bv);
        #pragma unroll
        for (int k = 0; k < 8; k++) bsp_s[tid][k] = bv[k];
    }
    __syncthreads();
    const int warp = tid >> 5, lane = tid & 31;
    if (warp < 2)
        #pragma unroll 1
        for (int o = warp * 5; o < warp * 5 + 5; o++) {
            float acc = 0.f;
            #pragma unroll
            for (int ii = 0; ii < 2; ii++) {
                int i = ii * 32 + lane;
                acc += silu_s[i] * base_w[o * 64 + i];
                const float4* sp = (const float4*)(spline_w + ((long)o * 64 + i) * 8);
                float4 s0 = sp[0], s1 = sp[1];
                float s8 = bsp_s[i][0] * s0.x + bsp_s[i][1] * s0.y + bsp_s[i][2] * s0.z + bsp_s[i][3] * s0.w
                         + bsp_s[i][4] * s1.x + bsp_s[i][5] * s1.y + bsp_s[i][6] * s1.z + bsp_s[i][7] * s1.w;
                acc += scaler[o * 64 + i] * s8;
            }
            #pragma unroll
            for (int off = 16; off; off >>= 1) acc += __shfl_xor_sync(0xffffffffu, acc, off);
            if (lane == 0) out[b * 10 + o] = acc;
        }
}

// ---------------- launch ----------------
extern "C" void kernel_launch(void* const* d_in, const int* in_sizes, int n_in,
                              void* d_out, int out_size) {
    const float* x      = (const float*)d_in[0];
    const float* g0_wih = (const float*)d_in[1];
    const float* g0_whh = (const float*)d_in[2];
    const float* g0_bih = (const float*)d_in[3];
    const float* g0_bhh = (const float*)d_in[4];
    const float* g1_wih = (const float*)d_in[5];
    const float* g1_whh = (const float*)d_in[6];
    const float* g1_bih = (const float*)d_in[7];
    const float* g1_bhh = (const float*)d_in[8];
    const float* lw_ih0  = (const float*)d_in[9];
    const float* lb_ih0  = (const float*)d_in[11];
    const float* lb_hh0  = (const float*)d_in[12];
    const float* lw_ih0r = (const float*)d_in[13];
    const float* lb_ih0r = (const float*)d_in[15];
    const float* lb_hh0r = (const float*)d_in[16];
    const float* lw_ih1  = (const float*)d_in[17];
    const float* lb_ih1  = (const float*)d_in[19];
    const float* lb_hh1  = (const float*)d_in[20];
    const float* lw_ih1r = (const float*)d_in[21];
    const float* lb_ih1r = (const float*)d_in[23];
    const float* lb_hh1r = (const float*)d_in[24];
    const float* kan1_base   = (const float*)d_in[25];
    const float* kan1_spline = (const float*)d_in[26];
    const float* kan1_scaler = (const float*)d_in[27];
    const float* kan2_base   = (const float*)d_in[28];
    const float* kan2_spline = (const float*)d_in[29];
    const float* kan2_scaler = (const float*)d_in[30];

    bf16 *h1h, *h1l; float *o0, *o1, *zz;
    cudaGetSymbolAddress((void**)&h1h, g_h1h);
    cudaGetSymbolAddress((void**)&h1l, g_h1l);
    cudaGetSymbolAddress((void**)&o0, g_o0);
    cudaGetSymbolAddress((void**)&o1, g_o1);
    cudaGetSymbolAddress((void**)&zz, g_z);

    cudaFuncSetAttribute(gru_tc, cudaFuncAttributeMaxDynamicSharedMemorySize, SMEM_TOTAL);

    xsplit_kernel<<<B_SZ * T_SZ * IN_SZ / (256 * 16), 256>>>(x);
    gru_tc<<<NB, NT, SMEM_TOTAL>>>(g0_wih, g0_whh, g0_bih, g0_bhh,
                                   g1_wih, g1_whh, g1_bih, g1_bhh);
    lstm_head_kernel<<<512, 256>>>(h1h, h1l, nullptr,
                                   lw_ih0, lb_ih0, lb_hh0, lw_ih0r, lb_ih0r, lb_hh0r, o0);
    lstm_head_kernel<<<512, 256>>>(nullptr, nullptr, o0,
                                   lw_ih1, lb_ih1, lb_hh1, lw_ih1r, lb_ih1r, lb_hh1r, o1);
    kan1_kernel<<<512, 256>>>(o1, kan1_base, kan1_spline, kan1_scaler, zz);
    kan2_kernel<<<512, 64>>>(zz, kan2_base, kan2_spline, kan2_scaler, (float*)d_out);
}

// round 12
// speedup vs baseline: 1.7719x; 1.1771x over previous
#include <cuda_runtime.h>
#include <cuda_bf16.h>
#include <math.h>

#define B_SZ 512
#define T_SZ 512
#define IN_SZ 128
#define NB 128
#define NT 384
typedef unsigned int u32;
typedef __nv_bfloat16 bf16;

// ---------------- globals (block-swizzled activation storage) ----------------
// blocks: 64 rows x 64 cols bf16 = 8KB, rows 128B, SW128-swizzled inside.
__device__ __align__(16) bf16 g_xh[T_SZ * 2 * 8 * 4096];   // [t][kc2][bg8][4096]
__device__ __align__(16) bf16 g_xl[T_SZ * 2 * 8 * 4096];
__device__ __align__(16) bf16 g_h0h[2][4 * 8 * 4096];      // [buf][kc4][bg8][4096]
__device__ __align__(16) bf16 g_h0l[2][4 * 8 * 4096];
__device__ __align__(16) bf16 g_h1h[2][4 * 8 * 4096];
__device__ __align__(16) bf16 g_h1l[2][4 * 8 * 4096];
__device__ float g_o0[B_SZ * 256], g_o1[B_SZ * 256], g_z[B_SZ * 64];
__device__ unsigned g_gc[8 * 32];
__device__ volatile unsigned g_gp[8 * 32];

__device__ __forceinline__ float sigmoidf_(float x) { return 1.f / (1.f + expf(-x)); }

// ---------------- smem map (bytes) ----------------
#define SM_BIAS 0          // 128 floats
#define SM_DRZ  512        // 64 x 36 f32
#define SM_DN0  9728       // 64 x 20 f32
#define SM_DN1  14848
#define SM_A    20480      // 2 bufs x (hi 8KB | lo 8KB)
#define SM_W    53248      // 178176 B of split weights
#define WO_L0I_H 0
#define WO_L0I_L 13056
#define WO_L0H_H 26112
#define WO_L0H_L 51456
#define WO_L1I_H 76800
#define WO_L1I_L 102144
#define WO_L1H_H 127488
#define WO_L1H_L 152832
#define SMEM_TOTAL 231424

// ---------------- PTX helpers ----------------
__device__ __forceinline__ void ldsm4(u32* r, u32 a) {
    asm volatile("ldmatrix.sync.aligned.m8n8.x4.shared.b16 {%0,%1,%2,%3}, [%4];"
        : "=r"(r[0]), "=r"(r[1]), "=r"(r[2]), "=r"(r[3]) : "r"(a));
}
__device__ __forceinline__ void mma16816(float* d, const u32* a, u32 b0, u32 b1) {
    asm volatile("mma.sync.aligned.m16n8k16.row.col.f32.bf16.bf16.f32 "
        "{%0,%1,%2,%3},{%4,%5,%6,%7},{%8,%9},{%0,%1,%2,%3};"
        : "+f"(d[0]), "+f"(d[1]), "+f"(d[2]), "+f"(d[3])
        : "r"(a[0]), "r"(a[1]), "r"(a[2]), "r"(a[3]), "r"(b0), "r"(b1));
}

// Monotonic group barrier over the 16 blocks sharing bg.
__device__ __forceinline__ void group_bar(int bg, unsigned& ph) {
    __syncthreads();
    if (threadIdx.x == 0) {
        __threadfence();
        unsigned p = ph;
        if (atomicAdd(&g_gc[bg * 32], 1u) == p * 16u + 15u) {
            __threadfence();
            g_gp[bg * 32] = p + 1u;
        } else {
            while (g_gp[bg * 32] < p + 1u) { }
            __threadfence();
        }
    }
    __syncthreads();
    ph += 1u;
}

// weight slice (48 rows = 3 gates x 16 units) -> bf16 hi/lo, row-major ld=K+8
__device__ void wsplit(const float* __restrict__ W, int K, int us,
                       char* dh, char* dl, int tid) {
    const int wld = K + 8;
    for (int i = tid; i < 48 * K; i += NT) {
        int n = i / K, k = i % K;
        float w = W[(long)((n >> 4) * 256 + us * 16 + (n & 15)) * K + k];
        bf16 h = __float2bfloat16(w);
        bf16 l = __float2bfloat16(w - __bfloat162float(h));
        ((bf16*)dh)[n * wld + k] = h;
        ((bf16*)dl)[n * wld + k] = l;
    }
}

// ---- staging: 1024 x 16B units per chunk ([hi 8KB | lo 8KB], pre-swizzled) ----
__device__ __forceinline__ void ldg_chunk(uint4* v, const bf16* bh, const bf16* bl, int tid) {
    #pragma unroll
    for (int j = 0; j < 3; j++) {
        int idx = tid + j * NT;
        if (idx < 1024) {
            const bf16* s = (idx & 512) ? bl : bh;
            v[j] = *(const uint4*)(s + (idx & 511) * 8);
        }
    }
}
__device__ __forceinline__ void sts_chunk(char* dst, const uint4* v, int tid) {
    #pragma unroll
    for (int j = 0; j < 3; j++) {
        int idx = tid + j * NT;
        if (idx < 1024) *(uint4*)(dst + idx * 16) = v[j];
    }
}

// ---- one 64-K chunk: 4 kt x (4 LDSM.x4 + 6 MMA) ----
__device__ __forceinline__ void compute_chunk(u32 aHi, u32 wH, u32 wL, u32 bOff,
                                              float* a0, float* a1,
                                              int arow128, int axor) {
    #pragma unroll
    for (int kt = 0; kt < 4; kt++) {
        u32 ao = (u32)arow128 + (u32)(axor ^ (kt << 5));
        u32 Ah[4], Al[4], Bh[4], Bl[4];
        ldsm4(Ah, aHi + ao);
        ldsm4(Al, aHi + 8192u + ao);
        u32 bo = bOff + (u32)(kt << 5);
        ldsm4(Bh, wH + bo);
        ldsm4(Bl, wL + bo);
        mma16816(a0, Ah, Bh[0], Bh[2]); mma16816(a1, Ah, Bh[1], Bh[3]);
        mma16816(a0, Ah, Bl[0], Bl[2]); mma16816(a1, Ah, Bl[1], Bl[3]);
        mma16816(a0, Al, Bh[0], Bh[2]); mma16816(a1, Al, Bh[1], Bh[3]);
    }
}

__device__ __forceinline__ void store_acc(float* D, int ld, int cb, int mt, int lane,
                                          const float* a0, const float* a1) {
    int r = mt * 16 + (lane >> 2), c = cb + (lane & 3) * 2;
    *(float2*)&D[r * ld + c]           = make_float2(a0[0], a0[1]);
    *(float2*)&D[(r + 8) * ld + c]     = make_float2(a0[2], a0[3]);
    *(float2*)&D[r * ld + c + 8]       = make_float2(a1[0], a1[1]);
    *(float2*)&D[(r + 8) * ld + c + 8] = make_float2(a1[2], a1[3]);
}

// ---- one layer-stream: n1 ih-chunks + n2 hh-chunks, pipelined staging ----
__device__ __forceinline__ void run_stream(
    const bf16* s1h, const bf16* s1l, int n1, u32 w1h, u32 w1l, int wld1,
    const bf16* s2h, const bf16* s2l, int n2, u32 w2h, u32 w2l,
    char* sm, u32 smA, int tid, int lane, int mt, int gate,
    int arow128, int axor) {
    const int nch = n1 + n2;
    float a0[4] = {0.f, 0.f, 0.f, 0.f}, a1[4] = {0.f, 0.f, 0.f, 0.f};
    const int brow = gate * 16 + ((lane >> 3) & 1) * 8 + (lane & 7);
    const int bsel = (lane >> 4) * 16;
    const u32 bb1 = (u32)(brow * wld1 * 2 + bsel);
    const u32 bb2 = (u32)(brow * 528 + bsel);
    float* Drz = (float*)(sm + SM_DRZ);
    float* Dn0 = (float*)(sm + SM_DN0);
    float* Dn1 = (float*)(sm + SM_DN1);

    uint4 v[3];
    ldg_chunk(v, s1h, s1l, tid);
    sts_chunk(sm + SM_A, v, tid);
    __syncthreads();
    #pragma unroll 1
    for (int c = 0; c < nch; c++) {
        if (c + 1 < nch) {
            const int cn = c + 1;
            const bf16* bh = (cn < n1) ? s1h + cn * 32768 : s2h + (cn - n1) * 32768;
            const bf16* bl = (cn < n1) ? s1l + cn * 32768 : s2l + (cn - n1) * 32768;
            ldg_chunk(v, bh, bl, tid);
        }
        const u32 abuf = smA + (u32)((c & 1) * 16384);
        if (c < n1) compute_chunk(abuf, w1h, w1l, bb1 + (u32)(c * 128), a0, a1, arow128, axor);
        else        compute_chunk(abuf, w2h, w2l, bb2 + (u32)((c - n1) * 128), a0, a1, arow128, axor);
        if (gate == 2 && c == n1 - 1) {
            store_acc(Dn0, 20, 0, mt, lane, a0, a1);
            #pragma unroll
            for (int q = 0; q < 4; q++) { a0[q] = 0.f; a1[q] = 0.f; }
        }
        if (c + 1 < nch) sts_chunk(sm + SM_A + ((c + 1) & 1) * 16384, v, tid);
        __syncthreads();
    }
    if (gate < 2) store_acc(Drz, 36, gate * 16, mt, lane, a0, a1);
    else          store_acc(Dn1, 20, 0, mt, lane, a0, a1);
}

// ---- epilogue: gate math, h written back as swizzled bf16 hi/lo blocks ----
__device__ __forceinline__ void epi_fn(char* sm, int L,
    const bf16* hih, const bf16* hil, bf16* hoh, bf16* hol,
    int us, int tid) {
    __syncthreads();
    if (tid < 128) {
        const float* Drz = (const float*)(sm + SM_DRZ);
        const float* Dn0 = (const float*)(sm + SM_DN0);
        const float* Dn1 = (const float*)(sm + SM_DN1);
        const float* sb  = (const float*)(sm + SM_BIAS) + L * 64;
        int row = tid >> 1, half = tid & 1;
        int cin = (us & 3) * 16 + half * 8;
        u32 off = (u32)(row * 128 + cin * 2);
        off ^= (off >> 3) & 0x70;
        uint4 hh4 = *(const uint4*)((const char*)hih + off);
        uint4 hl4 = *(const uint4*)((const char*)hil + off);
        const bf16* ph = (const bf16*)&hh4;
        const bf16* pl = (const bf16*)&hl4;
        uint4 oh4, ol4;
        bf16* oh = (bf16*)&oh4;
        bf16* ol = (bf16*)&ol4;
        #pragma unroll
        for (int j = 0; j < 8; j++) {
            int ul = half * 8 + j;
            float rr = sigmoidf_(Drz[row * 36 + ul] + sb[ul]);
            float zz = sigmoidf_(Drz[row * 36 + 16 + ul] + sb[16 + ul]);
            float nn = tanhf(Dn0[row * 20 + ul] + sb[32 + ul]
                             + rr * (Dn1[row * 20 + ul] + sb[48 + ul]));
            float hp = __bfloat162float(ph[j]) + __bfloat162float(pl[j]);
            float h = (1.f - zz) * nn + zz * hp;
            bf16 hb = __float2bfloat16(h);
            oh[j] = hb;
            ol[j] = __float2bfloat16(h - __bfloat162float(hb));
        }
        *(uint4*)((char*)hoh + off) = oh4;
        *(uint4*)((char*)hol + off) = ol4;
    }
    __syncthreads();
}

// one-shot: x -> swizzled bf16 hi/lo blocks  [t][kc][bg][64x64]
__global__ void __launch_bounds__(256) xsplit_kernel(const float* __restrict__ x) {
    for (int q = 0; q < 4; q++) {
        int u = (blockIdx.x * 256 + threadIdx.x) * 4 + q;   // 16B unit id
        int blk = u >> 9, lin = u & 511;
        int row = lin >> 3, c8 = lin & 7;
        int bg = blk & 7, tkc = blk >> 3, kc = tkc & 1, t = tkc >> 1;
        const float* src = x + ((long)(bg * 64 + row) * T_SZ + t) * IN_SZ + kc * 64 + c8 * 8;
        float4 v0 = *(const float4*)src;
        float4 v1 = *(const float4*)(src + 4);
        bf16 h[8], l[8];
        float f[8] = {v0.x, v0.y, v0.z, v0.w, v1.x, v1.y, v1.z, v1.w};
        #pragma unroll
        for (int j = 0; j < 8; j++) {
            h[j] = __float2bfloat16(f[j]);
            l[j] = __float2bfloat16(f[j] - __bfloat162float(h[j]));
        }
        u32 off = (u32)(row * 128 + c8 * 16);
        off ^= (off >> 3) & 0x70;
        *(uint4*)((char*)(g_xh + (long)blk * 4096) + off) = *(uint4*)h;
        *(uint4*)((char*)(g_xl + (long)blk * 4096) + off) = *(uint4*)l;
    }
}

// ---------------- persistent GRU scan ----------------
__global__ void __launch_bounds__(NT) gru_tc(
    const float* __restrict__ W0i, const float* __restrict__ W0h,
    const float* __restrict__ b0i, const float* __restrict__ b0h,
    const float* __restrict__ W1i, const float* __restrict__ W1h,
    const float* __restrict__ b1i, const float* __restrict__ b1h) {
    extern __shared__ char sm[];
    const u32 smb = (u32)__cvta_generic_to_shared(sm);
    const int tid = threadIdx.x;
    const int bg = blockIdx.x >> 4, us = blockIdx.x & 15;
    const int lane = tid & 31, warp = tid >> 5;
    const int mt = warp & 3, gate = warp >> 2;
    const int arow = mt * 16 + (lane & 15);
    const int arow128 = arow * 128;
    const int axor = ((lane >> 4) << 4) ^ ((arow & 7) << 4);
    const u32 smA = smb + SM_A;
    float* sbias = (float*)(sm + SM_BIAS);

    wsplit(W0i, 128, us, sm + SM_W + WO_L0I_H, sm + SM_W + WO_L0I_L, tid);
    wsplit(W0h, 256, us, sm + SM_W + WO_L0H_H, sm + SM_W + WO_L0H_L, tid);
    wsplit(W1i, 256, us, sm + SM_W + WO_L1I_H, sm + SM_W + WO_L1I_L, tid);
    wsplit(W1h, 256, us, sm + SM_W + WO_L1H_H, sm + SM_W + WO_L1H_L, tid);
    if (tid < 128) {
        int L = tid >> 6, part = (tid >> 4) & 3, ul = tid & 15;
        int u = us * 16 + ul;
        const float* bi = L ? b1i : b0i;
        const float* bh = L ? b1h : b0h;
        float val;
        if      (part == 0) val = bi[u] + bh[u];
        else if (part == 1) val = bi[256 + u] + bh[256 + u];
        else if (part == 2) val = bi[512 + u];
        else                val = bh[512 + u];
        sbias[L * 64 + part * 16 + ul] = val;
    }
    // zero initial h (buffer 0): this CTA's 64 rows x 16 cols in all 4 arrays
    {
        const long eb = (long)((us >> 2) * 8 + bg) * 4096;
        if (tid < 128) {
            int row = tid >> 1, half = tid & 1;
            int cin = (us & 3) * 16 + half * 8;
            u32 off = (u32)(row * 128 + cin * 2);
            off ^= (off >> 3) & 0x70;
            uint4 z = make_uint4(0, 0, 0, 0);
            *(uint4*)((char*)(g_h0h[0] + eb) + off) = z;
            *(uint4*)((char*)(g_h0l[0] + eb) + off) = z;
            *(uint4*)((char*)(g_h1h[0] + eb) + off) = z;
            *(uint4*)((char*)(g_h1l[0] + eb) + off) = z;
        }
    }
    unsigned ph = g_gp[bg * 32];
    group_bar(bg, ph);

    const long eb = (long)((us >> 2) * 8 + bg) * 4096;
    for (int t = 0; t < T_SZ; t++) {
        const int r = t & 1, w = r ^ 1;
        const bf16* xh = g_xh + ((long)t * 16 + bg) * 4096;
        const bf16* xl = g_xl + ((long)t * 16 + bg) * 4096;
        run_stream(xh, xl, 2, smb + SM_W + WO_L0I_H, smb + SM_W + WO_L0I_L, 136,
                   g_h0h[r] + bg * 4096, g_h0l[r] + bg * 4096, 4,
                   smb + SM_W + WO_L0H_H, smb + SM_W + WO_L0H_L,
                   sm, smA, tid, lane, mt, gate, arow128, axor);
        epi_fn(sm, 0, g_h0h[r] + eb, g_h0l[r] + eb, g_h0h[w] + eb, g_h0l[w] + eb, us, tid);
        group_bar(bg, ph);
        run_stream(g_h0h[w] + bg * 4096, g_h0l[w] + bg * 4096, 4,
                   smb + SM_W + WO_L1I_H, smb + SM_W + WO_L1I_L, 264,
                   g_h1h[r] + bg * 4096, g_h1l[r] + bg * 4096, 4,
                   smb + SM_W + WO_L1H_H, smb + SM_W + WO_L1H_L,
                   sm, smA, tid, lane, mt, gate, arow128, axor);
        epi_fn(sm, 1, g_h1h[r] + eb, g_h1l[r] + eb, g_h1h[w] + eb, g_h1l[w] + eb, us, tid);
    }
    // final h1 (t=511 odd -> w=0) in buffer 0 (block-swizzled layout)
}

// ---------------- tails ----------------
__global__ void __launch_bounds__(256) lstm_head_kernel(
    const bf16* __restrict__ sh, const bf16* __restrict__ sl, const float* __restrict__ sf,
    const float* __restrict__ Wf, const float* __restrict__ bif, const float* __restrict__ bhf,
    const float* __restrict__ Wr, const float* __restrict__ bir, const float* __restrict__ bhr,
    float* __restrict__ out) {
    __shared__ float ss[256];
    const int b = blockIdx.x, tid = threadIdx.x;
    const int warp = tid >> 5, lane = tid & 31;
    if (sh) {   // h1 in block-swizzled hi/lo layout
        int kc = tid >> 6, bgb = b >> 6;
        long blkb = (long)(kc * 8 + bgb) * 4096 * 2;
        u32 off = (u32)((b & 63) * 128 + (tid & 63) * 2);
        off ^= (off >> 3) & 0x70;
        ss[tid] = __bfloat162float(*(const bf16*)((const char*)sh + blkb + off))
                + __bfloat162float(*(const bf16*)((const char*)sl + blkb + off));
    } else {
        ss[tid] = sf[b * 256 + tid];
    }
    __syncthreads();
    #pragma unroll 1
    for (int oo = 0; oo < 32; oo++) {
        int idx = warp * 32 + oo;
        int hd = idx >> 7, j = idx & 127;
        const float* W = hd ? Wr : Wf;
        const float* bi = hd ? bir : bif;
        const float* bh = hd ? bhr : bhf;
        float di = 0.f, dg = 0.f, doo = 0.f;
        #pragma unroll
        for (int kk = 0; kk < 8; kk++) {
            int k = kk * 32 + lane;
            float sv = ss[k];
            di  += sv * W[(long)j * 256 + k];
            dg  += sv * W[(long)(256 + j) * 256 + k];
            doo += sv * W[(long)(384 + j) * 256 + k];
        }
        #pragma unroll
        for (int off = 16; off; off >>= 1) {
            di  += __shfl_xor_sync(0xffffffffu, di,  off);
            dg  += __shfl_xor_sync(0xffffffffu, dg,  off);
            doo += __shfl_xor_sync(0xffffffffu, doo, off);
        }
        if (lane == 0) {
            di  += bi[j] + bh[j];
            dg  += bi[256 + j] + bh[256 + j];
            doo += bi[384 + j] + bh[384 + j];
            float c = sigmoidf_(di) * tanhf(dg);
            out[b * 256 + hd * 128 + j] = sigmoidf_(doo) * tanhf(c);
        }
    }
}

__device__ __forceinline__ void bspl8(float x, float* bv) {
    const float h = 0.4f;
    float p[12];
    #pragma unroll
    for (int m = 0; m < 12; m++) p[m] = (float)(m - 3) * h - 1.0f;
    float b[11];
    #pragma unroll
    for (int j = 0; j < 11; j++) b[j] = (x >= p[j] && x < p[j + 1]) ? 1.f : 0.f;
    #pragma unroll
    for (int k = 1; k <= 3; k++)
        #pragma unroll
        for (int j = 0; j < 11 - k; j++)
            b[j] = (x - p[j]) / (p[j + k] - p[j]) * b[j]
                 + (p[j + k + 1] - x) / (p[j + k + 1] - p[j + 1]) * b[j + 1];
    #pragma unroll
    for (int j = 0; j < 8; j++) bv[j] = b[j];
}

__global__ void __launch_bounds__(256) kan1_kernel(
    const float* __restrict__ in, const float* __restrict__ base_w,
    const float* __restrict__ spline_w, const float* __restrict__ scaler,
    float* __restrict__ out) {
    __shared__ float silu_s[256];
    __shared__ float bsp_s[256][9];
    const int b = blockIdx.x, tid = threadIdx.x;
    const int warp = tid >> 5, lane = tid & 31;
    {
        float xv = in[b * 256 + tid];
        silu_s[tid] = xv / (1.f + expf(-xv));
        float bv[8]; bspl8(xv, bv);
        #pragma unroll
        for (int k = 0; k < 8; k++) bsp_s[tid][k] = bv[k];
    }
    __syncthreads();
    #pragma unroll 1
    for (int o = warp * 8; o < warp * 8 + 8; o++) {
        float acc = 0.f;
        #pragma unroll
        for (int ii = 0; ii < 8; ii++) {
            int i = ii * 32 + lane;
            acc += silu_s[i] * base_w[o * 256 + i];
            const float4* sp = (const float4*)(spline_w + ((long)o * 256 + i) * 8);
            float4 s0 = sp[0], s1 = sp[1];
            float s8 = bsp_s[i][0] * s0.x + bsp_s[i][1] * s0.y + bsp_s[i][2] * s0.z + bsp_s[i][3] * s0.w
                     + bsp_s[i][4] * s1.x + bsp_s[i][5] * s1.y + bsp_s[i][6] * s1.z + bsp_s[i][7] * s1.w;
            acc += scaler[o * 256 + i] * s8;
        }
        #pragma unroll
        for (int off = 16; off; off >>= 1) acc += __shfl_xor_sync(0xffffffffu, acc, off);
        if (lane == 0) out[b * 64 + o] = acc;
    }
}

__global__ void __launch_bounds__(64) kan2_kernel(
    const float* __restrict__ in, const float* __restrict__ base_w,
    const float* __restrict__ spline_w, const float* __restrict__ scaler,
    float* __restrict__ out) {
    __shared__ float silu_s[64];
    __shared__ float bsp_s[64][9];
    const int b = blockIdx.x, tid = threadIdx.x;
    {
        float xv = in[b * 64 + tid];
        silu_s[tid] = xv / (1.f + expf(-xv));
        float bv[8]; bspl8(xv, bv);
        #pragma unroll
        for (int k = 0; k < 8; k++) bsp_s[tid][k] = bv[k];
    }
    __syncthreads();
    const int warp = tid >> 5, lane = tid & 31;
    if (warp < 2)
        #pragma unroll 1
        for (int o = warp * 5; o < warp * 5 + 5; o++) {
            float acc = 0.f;
            #pragma unroll
            for (int ii = 0; ii < 2; ii++) {
                int i = ii * 32 + lane;
                acc += silu_s[i] * base_w[o * 64 + i];
                const float4* sp = (const float4*)(spline_w + ((long)o * 64 + i) * 8);
                float4 s0 = sp[0], s1 = sp[1];
                float s8 = bsp_s[i][0] * s0.x + bsp_s[i][1] * s0.y + bsp_s[i][2] * s0.z + bsp_s[i][3] * s0.w
                         + bsp_s[i][4] * s1.x + bsp_s[i][5] * s1.y + bsp_s[i][6] * s1.z + bsp_s[i][7] * s1.w;
                acc += scaler[o * 64 + i] * s8;
            }
            #pragma unroll
            for (int off = 16; off; off >>= 1) acc += __shfl_xor_sync(0xffffffffu, acc, off);
            if (lane == 0) out[b * 10 + o] = acc;
        }
}

// ---------------- launch ----------------
extern "C" void kernel_launch(void* const* d_in, const int* in_sizes, int n_in,
                              void* d_out, int out_size) {
    const float* x      = (const float*)d_in[0];
    const float* g0_wih = (const float*)d_in[1];
    const float* g0_whh = (const float*)d_in[2];
    const float* g0_bih = (const float*)d_in[3];
    const float* g0_bhh = (const float*)d_in[4];
    const float* g1_wih = (const float*)d_in[5];
    const float* g1_whh = (const float*)d_in[6];
    const float* g1_bih = (const float*)d_in[7];
    const float* g1_bhh = (const float*)d_in[8];
    const float* lw_ih0  = (const float*)d_in[9];
    const float* lb_ih0  = (const float*)d_in[11];
    const float* lb_hh0  = (const float*)d_in[12];
    const float* lw_ih0r = (const float*)d_in[13];
    const float* lb_ih0r = (const float*)d_in[15];
    const float* lb_hh0r = (const float*)d_in[16];
    const float* lw_ih1  = (const float*)d_in[17];
    const float* lb_ih1  = (const float*)d_in[19];
    const float* lb_hh1  = (const float*)d_in[20];
    const float* lw_ih1r = (const float*)d_in[21];
    const float* lb_ih1r = (const float*)d_in[23];
    const float* lb_hh1r = (const float*)d_in[24];
    const float* kan1_base   = (const float*)d_in[25];
    const float* kan1_spline = (const float*)d_in[26];
    const float* kan1_scaler = (const float*)d_in[27];
    const float* kan2_base   = (const float*)d_in[28];
    const float* kan2_spline = (const float*)d_in[29];
    const float* kan2_scaler = (const float*)d_in[30];

    bf16 *h1h, *h1l; float *o0, *o1, *zz;
    cudaGetSymbolAddress((void**)&h1h, g_h1h);
    cudaGetSymbolAddress((void**)&h1l, g_h1l);
    cudaGetSymbolAddress((void**)&o0, g_o0);
    cudaGetSymbolAddress((void**)&o1, g_o1);
    cudaGetSymbolAddress((void**)&zz, g_z);

    cudaFuncSetAttribute(gru_tc, cudaFuncAttributeMaxDynamicSharedMemorySize, SMEM_TOTAL);

    xsplit_kernel<<<4096, 256>>>(x);
    gru_tc<<<NB, NT, SMEM_TOTAL>>>(g0_wih, g0_whh, g0_bih, g0_bhh,
                                   g1_wih, g1_whh, g1_bih, g1_bhh);
    lstm_head_kernel<<<512, 256>>>(h1h, h1l, nullptr,
                                   lw_ih0, lb_ih0, lb_hh0, lw_ih0r, lb_ih0r, lb_hh0r, o0);
    lstm_head_kernel<<<512, 256>>>(nullptr, nullptr, o0,
                                   lw_ih1, lb_ih1, lb_hh1, lw_ih1r, lb_ih1r, lb_hh1r, o1);
    kan1_kernel<<<512, 256>>>(o1, kan1_base, kan1_spline, kan1_scaler, zz);
    kan2_kernel<<<512, 64>>>(zz, kan2_base, kan2_spline, kan2_scaler, (float*)d_out);
}

// round 13
// speedup vs baseline: 1.8843x; 1.0635x over previous
#include <cuda_runtime.h>
#include <cuda_bf16.h>
#include <math.h>

#define B_SZ 512
#define T_SZ 512
#define IN_SZ 128
#define NB 128
#define NT 384
typedef unsigned int u32;
typedef __nv_bfloat16 bf16;

// ---------------- globals (block-swizzled activation storage) ----------------
// blocks: 64 rows x 64 cols bf16 = 8KB, rows 128B, SW128-swizzled inside.
__device__ __align__(16) bf16 g_xh[T_SZ * 2 * 8 * 4096];   // [t][kc2][bg8][4096]
__device__ __align__(16) bf16 g_xl[T_SZ * 2 * 8 * 4096];
__device__ __align__(16) bf16 g_h0h[2][4 * 8 * 4096];      // [buf][kc4][bg8][4096]
__device__ __align__(16) bf16 g_h0l[2][4 * 8 * 4096];
__device__ __align__(16) bf16 g_h1h[2][4 * 8 * 4096];
__device__ __align__(16) bf16 g_h1l[2][4 * 8 * 4096];
__device__ float g_o0[B_SZ * 256], g_o1[B_SZ * 256], g_z[B_SZ * 64];
__device__ unsigned g_gc[8 * 32];
__device__ volatile unsigned g_gp[8 * 32];

__device__ __forceinline__ float sigmoidf_(float x) { return 1.f / (1.f + expf(-x)); }

// ---------------- smem map (bytes) ----------------
#define SM_BIAS 0          // 128 floats
#define SM_DRZ  512        // 64 x 36 f32
#define SM_DN0  9728       // 64 x 20 f32
#define SM_DN1  14848
#define SM_A    20480      // 2 bufs x (hi 8KB | lo 8KB)
#define SM_W    53248      // 178176 B of split weights
#define WO_L0I_H 0
#define WO_L0I_L 13056
#define WO_L0H_H 26112
#define WO_L0H_L 51456
#define WO_L1I_H 76800
#define WO_L1I_L 102144
#define WO_L1H_H 127488
#define WO_L1H_L 152832
#define SMEM_TOTAL 231424

// ---------------- PTX helpers ----------------
__device__ __forceinline__ void ldsm4(u32* r, u32 a) {
    asm volatile("ldmatrix.sync.aligned.m8n8.x4.shared.b16 {%0,%1,%2,%3}, [%4];"
        : "=r"(r[0]), "=r"(r[1]), "=r"(r[2]), "=r"(r[3]) : "r"(a));
}
__device__ __forceinline__ void mma16816(float* d, const u32* a, u32 b0, u32 b1) {
    asm volatile("mma.sync.aligned.m16n8k16.row.col.f32.bf16.bf16.f32 "
        "{%0,%1,%2,%3},{%4,%5,%6,%7},{%8,%9},{%0,%1,%2,%3};"
        : "+f"(d[0]), "+f"(d[1]), "+f"(d[2]), "+f"(d[3])
        : "r"(a[0]), "r"(a[1]), "r"(a[2]), "r"(a[3]), "r"(b0), "r"(b1));
}
#define CPA_COMMIT() asm volatile("cp.async.commit_group;" ::: "memory")
#define CPA_WAIT0()  asm volatile("cp.async.wait_group 0;" ::: "memory")

// Monotonic group barrier over the 16 blocks sharing bg.
__device__ __forceinline__ void group_bar(int bg, unsigned& ph) {
    __syncthreads();
    if (threadIdx.x == 0) {
        __threadfence();
        unsigned p = ph;
        if (atomicAdd(&g_gc[bg * 32], 1u) == p * 16u + 15u) {
            __threadfence();
            g_gp[bg * 32] = p + 1u;
        } else {
            while (g_gp[bg * 32] < p + 1u) { }
            __threadfence();
        }
    }
    __syncthreads();
    ph += 1u;
}

// weight slice (48 rows = 3 gates x 16 units) -> bf16 hi/lo, row-major ld=K+8
__device__ void wsplit(const float* __restrict__ W, int K, int us,
                       char* dh, char* dl, int tid) {
    const int wld = K + 8;
    for (int i = tid; i < 48 * K; i += NT) {
        int n = i / K, k = i % K;
        float w = W[(long)((n >> 4) * 256 + us * 16 + (n & 15)) * K + k];
        bf16 h = __float2bfloat16(w);
        bf16 l = __float2bfloat16(w - __bfloat162float(h));
        ((bf16*)dh)[n * wld + k] = h;
        ((bf16*)dl)[n * wld + k] = l;
    }
}

// ---- cp.async staging: 1024 x 16B units per chunk ([hi 8KB | lo 8KB]) ----
__device__ __forceinline__ void cpa_chunk(u32 dst, const bf16* bh, const bf16* bl, int tid) {
    #pragma unroll
    for (int j = 0; j < 3; j++) {
        int idx = tid + j * NT;
        if (idx < 1024) {
            const bf16* s = (idx & 512) ? bl : bh;
            asm volatile("cp.async.cg.shared.global [%0], [%1], 16;"
                :: "r"(dst + (u32)idx * 16u), "l"(s + (idx & 511) * 8) : "memory");
        }
    }
}

// ---- one 64-K chunk: 4 kt x (4 LDSM.x4 + 6 MMA) ----
__device__ __forceinline__ void compute_chunk(u32 aHi, u32 wH, u32 wL, u32 bOff,
                                              float* a0, float* a1,
                                              int arow128, int axor) {
    #pragma unroll
    for (int kt = 0; kt < 4; kt++) {
        u32 ao = (u32)arow128 + (u32)(axor ^ (kt << 5));
        u32 Ah[4], Al[4], Bh[4], Bl[4];
        ldsm4(Ah, aHi + ao);
        ldsm4(Al, aHi + 8192u + ao);
        u32 bo = bOff + (u32)(kt << 5);
        ldsm4(Bh, wH + bo);
        ldsm4(Bl, wL + bo);
        mma16816(a0, Ah, Bh[0], Bh[2]); mma16816(a1, Ah, Bh[1], Bh[3]);
        mma16816(a0, Ah, Bl[0], Bl[2]); mma16816(a1, Ah, Bl[1], Bl[3]);
        mma16816(a0, Al, Bh[0], Bh[2]); mma16816(a1, Al, Bh[1], Bh[3]);
    }
}

__device__ __forceinline__ void store_acc(float* D, int ld, int cb, int mt, int lane,
                                          const float* a0, const float* a1) {
    int r = mt * 16 + (lane >> 2), c = cb + (lane & 3) * 2;
    *(float2*)&D[r * ld + c]           = make_float2(a0[0], a0[1]);
    *(float2*)&D[(r + 8) * ld + c]     = make_float2(a0[2], a0[3]);
    *(float2*)&D[r * ld + c + 8]       = make_float2(a1[0], a1[1]);
    *(float2*)&D[(r + 8) * ld + c + 8] = make_float2(a1[2], a1[3]);
}

// ---- one layer-stream: n1 ih-chunks + n2 hh-chunks, cp.async pipelined ----
__device__ __forceinline__ void run_stream(
    const bf16* s1h, const bf16* s1l, int n1, u32 w1h, u32 w1l, int wld1,
    const bf16* s2h, const bf16* s2l, int n2, u32 w2h, u32 w2l,
    char* sm, u32 smA, int tid, int lane, int mt, int gate,
    int arow128, int axor) {
    const int nch = n1 + n2;
    float a0[4] = {0.f, 0.f, 0.f, 0.f}, a1[4] = {0.f, 0.f, 0.f, 0.f};
    const int brow = gate * 16 + ((lane >> 3) & 1) * 8 + (lane & 7);
    const int bsel = (lane >> 4) * 16;
    const u32 bb1 = (u32)(brow * wld1 * 2 + bsel);
    const u32 bb2 = (u32)(brow * 528 + bsel);
    float* Drz = (float*)(sm + SM_DRZ);
    float* Dn0 = (float*)(sm + SM_DN0);
    float* Dn1 = (float*)(sm + SM_DN1);

    cpa_chunk(smA, s1h, s1l, tid);
    CPA_COMMIT();
    CPA_WAIT0();
    __syncthreads();
    #pragma unroll 1
    for (int c = 0; c < nch; c++) {
        if (c + 1 < nch) {   // issue next-chunk DMA immediately after publish
            const int cn = c + 1;
            const bf16* bh = (cn < n1) ? s1h + cn * 32768 : s2h + (cn - n1) * 32768;
            const bf16* bl = (cn < n1) ? s1l + cn * 32768 : s2l + (cn - n1) * 32768;
            cpa_chunk(smA + (u32)((cn & 1) * 16384), bh, bl, tid);
            CPA_COMMIT();
        }
        const u32 abuf = smA + (u32)((c & 1) * 16384);
        if (c < n1) compute_chunk(abuf, w1h, w1l, bb1 + (u32)(c * 128), a0, a1, arow128, axor);
        else        compute_chunk(abuf, w2h, w2l, bb2 + (u32)((c - n1) * 128), a0, a1, arow128, axor);
        if (gate == 2 && c == n1 - 1) {
            store_acc(Dn0, 20, 0, mt, lane, a0, a1);
            #pragma unroll
            for (int q = 0; q < 4; q++) { a0[q] = 0.f; a1[q] = 0.f; }
        }
        if (c + 1 < nch) CPA_WAIT0();
        __syncthreads();
    }
    if (gate < 2) store_acc(Drz, 36, gate * 16, mt, lane, a0, a1);
    else          store_acc(Dn1, 20, 0, mt, lane, a0, a1);
}

// ---- epilogue: gate math, h written back as swizzled bf16 hi/lo blocks ----
// NOTE: no exit sync — D is not rewritten until deep inside the next stream
// (behind multiple loop syncs), and the next consumer of h sits behind either
// the group barrier (layer 0) or next step's barrier (layer 1).
__device__ __forceinline__ void epi_fn(char* sm, int L,
    const bf16* hih, const bf16* hil, bf16* hoh, bf16* hol,
    int us, int tid) {
    __syncthreads();   // D stores visible
    if (tid < 128) {
        const float* Drz = (const float*)(sm + SM_DRZ);
        const float* Dn0 = (const float*)(sm + SM_DN0);
        const float* Dn1 = (const float*)(sm + SM_DN1);
        const float* sb  = (const float*)(sm + SM_BIAS) + L * 64;
        int row = tid >> 1, half = tid & 1;
        int cin = (us & 3) * 16 + half * 8;
        u32 off = (u32)(row * 128 + cin * 2);
        off ^= (off >> 3) & 0x70;
        uint4 hh4 = *(const uint4*)((const char*)hih + off);
        uint4 hl4 = *(const uint4*)((const char*)hil + off);
        const bf16* ph = (const bf16*)&hh4;
        const bf16* pl = (const bf16*)&hl4;
        uint4 oh4, ol4;
        bf16* oh = (bf16*)&oh4;
        bf16* ol = (bf16*)&ol4;
        #pragma unroll
        for (int j = 0; j < 8; j++) {
            int ul = half * 8 + j;
            float rr = sigmoidf_(Drz[row * 36 + ul] + sb[ul]);
            float zz = sigmoidf_(Drz[row * 36 + 16 + ul] + sb[16 + ul]);
            float nn = tanhf(Dn0[row * 20 + ul] + sb[32 + ul]
                             + rr * (Dn1[row * 20 + ul] + sb[48 + ul]));
            float hp = __bfloat162float(ph[j]) + __bfloat162float(pl[j]);
            float h = (1.f - zz) * nn + zz * hp;
            bf16 hb = __float2bfloat16(h);
            oh[j] = hb;
            ol[j] = __float2bfloat16(h - __bfloat162float(hb));
        }
        *(uint4*)((char*)hoh + off) = oh4;
        *(uint4*)((char*)hol + off) = ol4;
    }
}

// one-shot: x -> swizzled bf16 hi/lo blocks  [t][kc][bg][64x64]
__global__ void __launch_bounds__(256) xsplit_kernel(const float* __restrict__ x) {
    for (int q = 0; q < 4; q++) {
        int u = (blockIdx.x * 256 + threadIdx.x) * 4 + q;   // 16B unit id
        int blk = u >> 9, lin = u & 511;
        int row = lin >> 3, c8 = lin & 7;
        int bg = blk & 7, tkc = blk >> 3, kc = tkc & 1, t = tkc >> 1;
        const float* src = x + ((long)(bg * 64 + row) * T_SZ + t) * IN_SZ + kc * 64 + c8 * 8;
        float4 v0 = *(const float4*)src;
        float4 v1 = *(const float4*)(src + 4);
        bf16 h[8], l[8];
        float f[8] = {v0.x, v0.y, v0.z, v0.w, v1.x, v1.y, v1.z, v1.w};
        #pragma unroll
        for (int j = 0; j < 8; j++) {
            h[j] = __float2bfloat16(f[j]);
            l[j] = __float2bfloat16(f[j] - __bfloat162float(h[j]));
        }
        u32 off = (u32)(row * 128 + c8 * 16);
        off ^= (off >> 3) & 0x70;
        *(uint4*)((char*)(g_xh + (long)blk * 4096) + off) = *(uint4*)h;
        *(uint4*)((char*)(g_xl + (long)blk * 4096) + off) = *(uint4*)l;
    }
}

// ---------------- persistent GRU scan ----------------
__global__ void __launch_bounds__(NT) gru_tc(
    const float* __restrict__ W0i, const float* __restrict__ W0h,
    const float* __restrict__ b0i, const float* __restrict__ b0h,
    const float* __restrict__ W1i, const float* __restrict__ W1h,
    const float* __restrict__ b1i, const float* __restrict__ b1h) {
    extern __shared__ char sm[];
    const u32 smb = (u32)__cvta_generic_to_shared(sm);
    const int tid = threadIdx.x;
    const int bg = blockIdx.x >> 4, us = blockIdx.x & 15;
    const int lane = tid & 31, warp = tid >> 5;
    const int mt = warp & 3, gate = warp >> 2;
    const int arow = mt * 16 + (lane & 15);
    const int arow128 = arow * 128;
    const int axor = ((lane >> 4) << 4) ^ ((arow & 7) << 4);
    const u32 smA = smb + SM_A;
    float* sbias = (float*)(sm + SM_BIAS);

    wsplit(W0i, 128, us, sm + SM_W + WO_L0I_H, sm + SM_W + WO_L0I_L, tid);
    wsplit(W0h, 256, us, sm + SM_W + WO_L0H_H, sm + SM_W + WO_L0H_L, tid);
    wsplit(W1i, 256, us, sm + SM_W + WO_L1I_H, sm + SM_W + WO_L1I_L, tid);
    wsplit(W1h, 256, us, sm + SM_W + WO_L1H_H, sm + SM_W + WO_L1H_L, tid);
    if (tid < 128) {
        int L = tid >> 6, part = (tid >> 4) & 3, ul = tid & 15;
        int u = us * 16 + ul;
        const float* bi = L ? b1i : b0i;
        const float* bh = L ? b1h : b0h;
        float val;
        if      (part == 0) val = bi[u] + bh[u];
        else if (part == 1) val = bi[256 + u] + bh[256 + u];
        else if (part == 2) val = bi[512 + u];
        else                val = bh[512 + u];
        sbias[L * 64 + part * 16 + ul] = val;
    }
    // zero initial h (buffer 0): this CTA's 64 rows x 16 cols in all 4 arrays
    {
        const long eb = (long)((us >> 2) * 8 + bg) * 4096;
        if (tid < 128) {
            int row = tid >> 1, half = tid & 1;
            int cin = (us & 3) * 16 + half * 8;
            u32 off = (u32)(row * 128 + cin * 2);
            off ^= (off >> 3) & 0x70;
            uint4 z = make_uint4(0, 0, 0, 0);
            *(uint4*)((char*)(g_h0h[0] + eb) + off) = z;
            *(uint4*)((char*)(g_h0l[0] + eb) + off) = z;
            *(uint4*)((char*)(g_h1h[0] + eb) + off) = z;
            *(uint4*)((char*)(g_h1l[0] + eb) + off) = z;
        }
    }
    unsigned ph = g_gp[bg * 32];
    group_bar(bg, ph);

    const long eb = (long)((us >> 2) * 8 + bg) * 4096;
    for (int t = 0; t < T_SZ; t++) {
        const int r = t & 1, w = r ^ 1;
        const bf16* xh = g_xh + ((long)t * 16 + bg) * 4096;
        const bf16* xl = g_xl + ((long)t * 16 + bg) * 4096;
        run_stream(xh, xl, 2, smb + SM_W + WO_L0I_H, smb + SM_W + WO_L0I_L, 136,
                   g_h0h[r] + bg * 4096, g_h0l[r] + bg * 4096, 4,
                   smb + SM_W + WO_L0H_H, smb + SM_W + WO_L0H_L,
                   sm, smA, tid, lane, mt, gate, arow128, axor);
        epi_fn(sm, 0, g_h0h[r] + eb, g_h0l[r] + eb, g_h0h[w] + eb, g_h0l[w] + eb, us, tid);
        group_bar(bg, ph);   // peers' h0(t) visible; includes the block-wide sync
        run_stream(g_h0h[w] + bg * 4096, g_h0l[w] + bg * 4096, 4,
                   smb + SM_W + WO_L1I_H, smb + SM_W + WO_L1I_L, 264,
                   g_h1h[r] + bg * 4096, g_h1l[r] + bg * 4096, 4,
                   smb + SM_W + WO_L1H_H, smb + SM_W + WO_L1H_L,
                   sm, smA, tid, lane, mt, gate, arow128, axor);
        epi_fn(sm, 1, g_h1h[r] + eb, g_h1l[r] + eb, g_h1h[w] + eb, g_h1l[w] + eb, us, tid);
        __syncthreads();   // h1 epi writes ordered before next step's staging reuse
    }
    // final h1 (t=511 odd -> w=0) in buffer 0 (block-swizzled layout)
}

// ---------------- tails ----------------
__global__ void __launch_bounds__(256) lstm_head_kernel(
    const bf16* __restrict__ sh, const bf16* __restrict__ sl, const float* __restrict__ sf,
    const float* __restrict__ Wf, const float* __restrict__ bif, const float* __restrict__ bhf,
    const float* __restrict__ Wr, const float* __restrict__ bir, const float* __restrict__ bhr,
    float* __restrict__ out) {
    __shared__ float ss[256];
    const int b = blockIdx.x, tid = threadIdx.x;
    const int warp = tid >> 5, lane = tid & 31;
    if (sh) {   // h1 in block-swizzled hi/lo layout
        int kc = tid >> 6, bgb = b >> 6;
        long blkb = (long)(kc * 8 + bgb) * 4096 * 2;
        u32 off = (u32)((b & 63) * 128 + (tid & 63) * 2);
        off ^= (off >> 3) & 0x70;
        ss[tid] = __bfloat162float(*(const bf16*)((const char*)sh + blkb + off))
                + __bfloat162float(*(const bf16*)((const char*)sl + blkb + off));
    } else {
        ss[tid] = sf[b * 256 + tid];
    }
    __syncthreads();
    #pragma unroll 1
    for (int oo = 0; oo < 32; oo++) {
        int idx = warp * 32 + oo;
        int hd = idx >> 7, j = idx & 127;
        const float* W = hd ? Wr : Wf;
        const float* bi = hd ? bir : bif;
        const float* bh = hd ? bhr : bhf;
        float di = 0.f, dg = 0.f, doo = 0.f;
        #pragma unroll
        for (int kk = 0; kk < 8; kk++) {
            int k = kk * 32 + lane;
            float sv = ss[k];
            di  += sv * W[(long)j * 256 + k];
            dg  += sv * W[(long)(256 + j) * 256 + k];
            doo += sv * W[(long)(384 + j) * 256 + k];
        }
        #pragma unroll
        for (int off = 16; off; off >>= 1) {
            di  += __shfl_xor_sync(0xffffffffu, di,  off);
            dg  += __shfl_xor_sync(0xffffffffu, dg,  off);
            doo += __shfl_xor_sync(0xffffffffu, doo, off);
        }
        if (lane == 0) {
            di  += bi[j] + bh[j];
            dg  += bi[256 + j] + bh[256 + j];
            doo += bi[384 + j] + bh[384 + j];
            float c = sigmoidf_(di) * tanhf(dg);
            out[b * 256 + hd * 128 + j] = sigmoidf_(doo) * tanhf(c);
        }
    }
}

__device__ __forceinline__ void bspl8(float x, float* bv) {
    const float h = 0.4f;
    float p[12];
    #pragma unroll
    for (int m = 0; m < 12; m++) p[m] = (float)(m - 3) * h - 1.0f;
    float b[11];
    #pragma unroll
    for (int j = 0; j < 11; j++) b[j] = (x >= p[j] && x < p[j + 1]) ? 1.f : 0.f;
    #pragma unroll
    for (int k = 1; k <= 3; k++)
        #pragma unroll
        for (int j = 0; j < 11 - k; j++)
            b[j] = (x - p[j]) / (p[j + k] - p[j]) * b[j]
                 + (p[j + k + 1] - x) / (p[j + k + 1] - p[j + 1]) * b[j + 1];
    #pragma unroll
    for (int j = 0; j < 8; j++) bv[j] = b[j];
}

__global__ void __launch_bounds__(256) kan1_kernel(
    const float* __restrict__ in, const float* __restrict__ base_w,
    const float* __restrict__ spline_w, const float* __restrict__ scaler,
    float* __restrict__ out) {
    __shared__ float silu_s[256];
    __shared__ float bsp_s[256][9];
    const int b = blockIdx.x, tid = threadIdx.x;
    const int warp = tid >> 5, lane = tid & 31;
    {
        float xv = in[b * 256 + tid];
        silu_s[tid] = xv / (1.f + expf(-xv));
        float bv[8]; bspl8(xv, bv);
        #pragma unroll
        for (int k = 0; k < 8; k++) bsp_s[tid][k] = bv[k];
    }
    __syncthreads();
    #pragma unroll 1
    for (int o = warp * 8; o < warp * 8 + 8; o++) {
        float acc = 0.f;
        #pragma unroll
        for (int ii = 0; ii < 8; ii++) {
            int i = ii * 32 + lane;
            acc += silu_s[i] * base_w[o * 256 + i];
            const float4* sp = (const float4*)(spline_w + ((long)o * 256 + i) * 8);
            float4 s0 = sp[0], s1 = sp[1];
            float s8 = bsp_s[i][0] * s0.x + bsp_s[i][1] * s0.y + bsp_s[i][2] * s0.z + bsp_s[i][3] * s0.w
                     + bsp_s[i][4] * s1.x + bsp_s[i][5] * s1.y + bsp_s[i][6] * s1.z + bsp_s[i][7] * s1.w;
            acc += scaler[o * 256 + i] * s8;
        }
        #pragma unroll
        for (int off = 16; off; off >>= 1) acc += __shfl_xor_sync(0xffffffffu, acc, off);
        if (lane == 0) out[b * 64 + o] = acc;
    }
}

__global__ void __launch_bounds__(64) kan2_kernel(
    const float* __restrict__ in, const float* __restrict__ base_w,
    const float* __restrict__ spline_w, const float* __restrict__ scaler,
    float* __restrict__ out) {
    __shared__ float silu_s[64];
    __shared__ float bsp_s[64][9];
    const int b = blockIdx.x, tid = threadIdx.x;
    {
        float xv = in[b * 64 + tid];
        silu_s[tid] = xv / (1.f + expf(-xv));
        float bv[8]; bspl8(xv, bv);
        #pragma unroll
        for (int k = 0; k < 8; k++) bsp_s[tid][k] = bv[k];
    }
    __syncthreads();
    const int warp = tid >> 5, lane = tid & 31;
    if (warp < 2)
        #pragma unroll 1
        for (int o = warp * 5; o < warp * 5 + 5; o++) {
            float acc = 0.f;
            #pragma unroll
            for (int ii = 0; ii < 2; ii++) {
                int i = ii * 32 + lane;
                acc += silu_s[i] * base_w[o * 64 + i];
                const float4* sp = (const float4*)(spline_w + ((long)o * 64 + i) * 8);
                float4 s0 = sp[0], s1 = sp[1];
                float s8 = bsp_s[i][0] * s0.x + bsp_s[i][1] * s0.y + bsp_s[i][2] * s0.z + bsp_s[i][3] * s0.w
                         + bsp_s[i][4] * s1.x + bsp_s[i][5] * s1.y + bsp_s[i][6] * s1.z + bsp_s[i][7] * s1.w;
                acc += scaler[o * 64 + i] * s8;
            }
            #pragma unroll
            for (int off = 16; off; off >>= 1) acc += __shfl_xor_sync(0xffffffffu, acc, off);
            if (lane == 0) out[b * 10 + o] = acc;
        }
}

// ---------------- launch ----------------
extern "C" void kernel_launch(void* const* d_in, const int* in_sizes, int n_in,
                              void* d_out, int out_size) {
    const float* x      = (const float*)d_in[0];
    const float* g0_wih = (const float*)d_in[1];
    const float* g0_whh = (const float*)d_in[2];
    const float* g0_bih = (const float*)d_in[3];
    const float* g0_bhh = (const float*)d_in[4];
    const float* g1_wih = (const float*)d_in[5];
    const float* g1_whh = (const float*)d_in[6];
    const float* g1_bih = (const float*)d_in[7];
    const float* g1_bhh = (const float*)d_in[8];
    const float* lw_ih0  = (const float*)d_in[9];
    const float* lb_ih0  = (const float*)d_in[11];
    const float* lb_hh0  = (const float*)d_in[12];
    const float* lw_ih0r = (const float*)d_in[13];
    const float* lb_ih0r = (const float*)d_in[15];
    const float* lb_hh0r = (const float*)d_in[16];
    const float* lw_ih1  = (const float*)d_in[17];
    const float* lb_ih1  = (const float*)d_in[19];
    const float* lb_hh1  = (const float*)d_in[20];
    const float* lw_ih1r = (const float*)d_in[21];
    const float* lb_ih1r = (const float*)d_in[23];
    const float* lb_hh1r = (const float*)d_in[24];
    const float* kan1_base   = (const float*)d_in[25];
    const float* kan1_spline = (const float*)d_in[26];
    const float* kan1_scaler = (const float*)d_in[27];
    const float* kan2_base   = (const float*)d_in[28];
    const float* kan2_spline = (const float*)d_in[29];
    const float* kan2_scaler = (const float*)d_in[30];

    bf16 *h1h, *h1l; float *o0, *o1, *zz;
    cudaGetSymbolAddress((void**)&h1h, g_h1h);
    cudaGetSymbolAddress((void**)&h1l, g_h1l);
    cudaGetSymbolAddress((void**)&o0, g_o0);
    cudaGetSymbolAddress((void**)&o1, g_o1);
    cudaGetSymbolAddress((void**)&zz, g_z);

    cudaFuncSetAttribute(gru_tc, cudaFuncAttributeMaxDynamicSharedMemorySize, SMEM_TOTAL);

    xsplit_kernel<<<4096, 256>>>(x);
    gru_tc<<<NB, NT, SMEM_TOTAL>>>(g0_wih, g0_whh, g0_bih, g0_bhh,
                                   g1_wih, g1_whh, g1_bih, g1_bhh);
    lstm_head_kernel<<<512, 256>>>(h1h, h1l, nullptr,
                                   lw_ih0, lb_ih0, lb_hh0, lw_ih0r, lb_ih0r, lb_hh0r, o0);
    lstm_head_kernel<<<512, 256>>>(nullptr, nullptr, o0,
                                   lw_ih1, lb_ih1, lb_hh1, lw_ih1r, lb_ih1r, lb_hh1r, o1);
    kan1_kernel<<<512, 256>>>(o1, kan1_base, kan1_spline, kan1_scaler, zz);
    kan2_kernel<<<512, 64>>>(zz, kan2_base, kan2_spline, kan2_scaler, (float*)d_out);
}